// round 9
// baseline (speedup 1.0000x reference)
#include <cuda_runtime.h>

#define NT 512

// B=256, T=16, O=32, E=32, I=32, H=HL=64, TE=512, EI=64, P=496
// One CTA = two independent 256-thread halves (one batch each), desynced via
// named barriers. grid=128, occupancy 1.

struct Params {
    const float* z;
    const float *ee1_w,*ee1_b,*ee2_w,*ee2_b,*ee3_w,*ee3_b;
    const float *ne1_w,*ne1_b,*ne2_w,*ne2_b,*ne3_w,*ne3_b,*ne4_w,*ne4_b;
    const float *le1_w,*le1_b,*le2_w,*le2_b,*le3_w,*le3_b;
    const float *lt1_w,*lt1_b,*lt2_w,*lt2_b,*lt3_w,*lt3_b,*lt4_w,*lt4_b,*lt5_w,*lt5_b;
    float* out;
    int t_future;
};

__device__ __forceinline__ void bsync(int id) {
    asm volatile("bar.sync %0, 256;" :: "r"(id) : "memory");
}

__device__ __forceinline__ void fma4(float acc[4], float a, const float4& w) {
    acc[0] = fmaf(a, w.x, acc[0]);
    acc[1] = fmaf(a, w.y, acc[1]);
    acc[2] = fmaf(a, w.z, acc[2]);
    acc[3] = fmaf(a, w.w, acc[3]);
}

// out[32][64] (opt +=) = in[32][IN] @ W[IN][64] (+bias) (opt relu). 256 thr: 2r x 4c.
template<int IN, bool ACC, bool RELU>
__device__ __forceinline__ void layer32x64(const float* __restrict__ in,
                                           const float* __restrict__ W,
                                           const float* __restrict__ bias,
                                           float* __restrict__ out, int ltid)
{
    const int c0 = (ltid & 15) * 4;
    const int r0 = (ltid >> 4) * 2;
    float acc0[4], acc1[4];
    if (ACC) {
#pragma unroll
        for (int j = 0; j < 4; j++) {
            acc0[j] = out[r0 * 64 + c0 + j];
            acc1[j] = out[(r0 + 1) * 64 + c0 + j];
        }
    } else {
#pragma unroll
        for (int j = 0; j < 4; j++) {
            float bv = bias ? bias[c0 + j] : 0.f;
            acc0[j] = bv; acc1[j] = bv;
        }
    }
    const float* in0 = in + r0 * IN;
    const float* in1 = in0 + IN;
#pragma unroll 4
    for (int k = 0; k < IN; k += 4) {
        float4 a0 = *(const float4*)(in0 + k);
        float4 a1 = *(const float4*)(in1 + k);
        float4 w0 = *(const float4*)(W + (k + 0) * 64 + c0);
        float4 w1 = *(const float4*)(W + (k + 1) * 64 + c0);
        float4 w2 = *(const float4*)(W + (k + 2) * 64 + c0);
        float4 w3 = *(const float4*)(W + (k + 3) * 64 + c0);
        fma4(acc0, a0.x, w0); fma4(acc0, a0.y, w1); fma4(acc0, a0.z, w2); fma4(acc0, a0.w, w3);
        fma4(acc1, a1.x, w0); fma4(acc1, a1.y, w1); fma4(acc1, a1.z, w2); fma4(acc1, a1.w, w3);
    }
#pragma unroll
    for (int j = 0; j < 4; j++) {
        float v0 = acc0[j], v1 = acc1[j];
        if (RELU) { v0 = fmaxf(v0, 0.f); v1 = fmaxf(v1, 0.f); }
        out[r0 * 64 + c0 + j] = v0;
        out[(r0 + 1) * 64 + c0 + j] = v1;
    }
}

#define H2S 68

// h2[64][H2S] = relu(h1[64][64] @ W[64][64] + b2). 256 thr: 4r x 4c.
__device__ __forceinline__ void gemm64(const float* __restrict__ A,
                                       const float* __restrict__ W,
                                       const float* __restrict__ b2,
                                       float* __restrict__ C, int ltid)
{
    const int c0 = (ltid & 15) * 4;
    const int r0 = (ltid >> 4) * 4;
    float acc[4][4];
#pragma unroll
    for (int j = 0; j < 4; j++) {
        float bv = b2[c0 + j];
#pragma unroll
        for (int i = 0; i < 4; i++) acc[i][j] = bv;
    }
#pragma unroll 2
    for (int k = 0; k < 64; k += 4) {
        float4 w0 = *(const float4*)(W + (k + 0) * 64 + c0);
        float4 w1 = *(const float4*)(W + (k + 1) * 64 + c0);
        float4 w2 = *(const float4*)(W + (k + 2) * 64 + c0);
        float4 w3 = *(const float4*)(W + (k + 3) * 64 + c0);
#pragma unroll
        for (int i = 0; i < 4; i++) {
            float4 a = *(const float4*)(A + (r0 + i) * 64 + k);
            fma4(acc[i], a.x, w0); fma4(acc[i], a.y, w1);
            fma4(acc[i], a.z, w2); fma4(acc[i], a.w, w3);
        }
    }
#pragma unroll
    for (int i = 0; i < 4; i++)
#pragma unroll
        for (int j = 0; j < 4; j++)
            C[(r0 + i) * H2S + c0 + j] = fmaxf(acc[i][j], 0.f);
}

// agg[32][64] = G[32][64] @ W3[64][64] + (31-2n)*b3
__device__ __forceinline__ void aggGemm(const float* __restrict__ G,
                                        const float* __restrict__ W3,
                                        const float* __restrict__ b3,
                                        float* __restrict__ agg, int ltid)
{
    const int c0 = (ltid & 15) * 4;
    const int r0 = (ltid >> 4) * 2;
    const float sc0 = (float)(31 - 2 * r0);
    const float sc1 = (float)(31 - 2 * (r0 + 1));
    float acc0[4], acc1[4];
#pragma unroll
    for (int j = 0; j < 4; j++) {
        float bv = b3[c0 + j];
        acc0[j] = sc0 * bv; acc1[j] = sc1 * bv;
    }
    const float* g0 = G + r0 * 64;
    const float* g1 = g0 + 64;
#pragma unroll 4
    for (int k = 0; k < 64; k += 4) {
        float4 a0 = *(const float4*)(g0 + k);
        float4 a1 = *(const float4*)(g1 + k);
        float4 w0 = *(const float4*)(W3 + (k + 0) * 64 + c0);
        float4 w1 = *(const float4*)(W3 + (k + 1) * 64 + c0);
        float4 w2 = *(const float4*)(W3 + (k + 2) * 64 + c0);
        float4 w3 = *(const float4*)(W3 + (k + 3) * 64 + c0);
        fma4(acc0, a0.x, w0); fma4(acc0, a0.y, w1); fma4(acc0, a0.z, w2); fma4(acc0, a0.w, w3);
        fma4(acc1, a1.x, w0); fma4(acc1, a1.y, w1); fma4(acc1, a1.z, w2); fma4(acc1, a1.w, w3);
    }
#pragma unroll
    for (int j = 0; j < 4; j++) {
        agg[r0 * 64 + c0 + j] = acc0[j];
        agg[(r0 + 1) * 64 + c0 + j] = acc1[j];
    }
}

// small layer with 2-accumulator k-split: out[32][OUT] = relu?(in[32][IN] @ W + b)
__device__ __forceinline__ void layer_small(const float* __restrict__ in, int IN,
                                            const float* __restrict__ W,
                                            const float* __restrict__ bias,
                                            float* __restrict__ out, int OUT,
                                            bool relu, int ltid)
{
    for (int idx = ltid; idx < 32 * OUT; idx += 256) {
        int r = idx / OUT, c = idx % OUT;
        float a0 = bias[c], a1 = 0.f;
        const float* inr = in + r * IN;
#pragma unroll 4
        for (int k = 0; k < IN; k += 2) {
            a0 = fmaf(inr[k],     W[k * OUT + c],       a0);
            a1 = fmaf(inr[k + 1], W[(k + 1) * OUT + c], a1);
        }
        float v = a0 + a1;
        out[idx] = relu ? fmaxf(v, 0.f) : v;
    }
}

// streamed k-chunk accumulate: acc[2rows][4cols] += s[32][64] @ Wg[64][64]
__device__ __forceinline__ void acc_chunk(const float* __restrict__ s,
                                          const float* __restrict__ Wg,
                                          float acc0[4], float acc1[4],
                                          int r0, int c0)
{
    const float* in0 = s + r0 * 64;
    const float* in1 = in0 + 64;
#pragma unroll 4
    for (int k = 0; k < 64; k += 4) {
        float4 a0 = *(const float4*)(in0 + k);
        float4 a1 = *(const float4*)(in1 + k);
        float4 w0 = *(const float4*)(Wg + (k + 0) * 64 + c0);
        float4 w1 = *(const float4*)(Wg + (k + 1) * 64 + c0);
        float4 w2 = *(const float4*)(Wg + (k + 2) * 64 + c0);
        float4 w3 = *(const float4*)(Wg + (k + 3) * 64 + c0);
        fma4(acc0, a0.x, w0); fma4(acc0, a0.y, w1); fma4(acc0, a0.z, w2); fma4(acc0, a0.w, w3);
        fma4(acc1, a1.x, w0); fma4(acc1, a1.y, w1); fma4(acc1, a1.z, w2); fma4(acc1, a1.w, w3);
    }
}

// edge block (one batch, 256 threads, named barrier). bias b1 pre-folded into ya.
__device__ __forceinline__ void edge_block(const float* ya, const float* yb,
                                           const float* __restrict__ W2,
                                           const float* __restrict__ b2,
                                           const float* __restrict__ W3,
                                           const float* __restrict__ b3,
                                           float* h1, float* h2, float* Gs, float* agg,
                                           const unsigned char* ii, const unsigned char* jj,
                                           const unsigned short* jl,
                                           int ltid, int barid)
{
    const int n   = ltid >> 3;          // 0..31
    const int c0s = (ltid & 7) * 8;
    const int rs    = n * 31 - ((n * (n - 1)) >> 1);
    const int iiend = rs + 31 - n;
    float g[8];
#pragma unroll
    for (int j = 0; j < 8; j++) g[j] = 0.f;
    int kcur = 0;

#pragma unroll 1
    for (int ch = 0; ch < 8; ch++) {
        const int p0 = ch * 64;
        for (int e = ltid; e < 64 * 64; e += 256) {
            int pl = e >> 6, c = e & 63;
            int p = p0 + pl;
            h1[e] = fmaxf(ya[ii[p] * 64 + c] + yb[jj[p] * 64 + c], 0.f);
        }
        bsync(barid);
        gemm64(h1, W2, b2, h2, ltid);
        bsync(barid);
        // signed sparse scatter into register G
        int lo = max(rs, p0), hi = min(iiend, p0 + 64);
        for (int p = lo; p < hi; p++) {
            const float* r = h2 + (p - p0) * H2S + c0s;
            float4 v0 = *(const float4*)(r);
            float4 v1 = *(const float4*)(r + 4);
            g[0] += v0.x; g[1] += v0.y; g[2] += v0.z; g[3] += v0.w;
            g[4] += v1.x; g[5] += v1.y; g[6] += v1.z; g[7] += v1.w;
        }
        while (kcur < n) {
            int p = jl[(n << 5) + kcur];
            if (p >= p0 + 64) break;
            const float* r = h2 + (p - p0) * H2S + c0s;
            float4 v0 = *(const float4*)(r);
            float4 v1 = *(const float4*)(r + 4);
            g[0] -= v0.x; g[1] -= v0.y; g[2] -= v0.z; g[3] -= v0.w;
            g[4] -= v1.x; g[5] -= v1.y; g[6] -= v1.z; g[7] -= v1.w;
            kcur++;
        }
    }
#pragma unroll
    for (int j = 0; j < 8; j++) Gs[n * 64 + c0s + j] = g[j];
    bsync(barid);
    aggGemm(Gs, W3, b3, agg, ltid);
    bsync(barid);
}

// smem layout (float offsets)
#define OFF_H1    0        // 2 x 4096
#define OFF_H2    8192     // 2 x 4352
#define OFF_YA    16896    // 2 x 2048
#define OFF_YB    20992
#define OFF_AGG   25088
#define OFF_ZC    29184
#define OFF_WLE1  33280    // 128*64
#define OFF_WLE2  41472    // 64*64
#define OFF_WLE3  45568    // 64*64
#define SMEM_FLOATS 49664
#define SMEM_BYTES  (SMEM_FLOATS * 4 + 2048 + 1024)

__global__ void __launch_bounds__(NT, 1)
RelationalLatentDynamics_82849919140105_kernel(Params P)
{
    extern __shared__ float sm[];
    const int tid  = threadIdx.x;
    const int half = tid >> 8;           // 0 or 1
    const int ltid = tid & 255;
    const int barid = 1 + half;

    float* h1  = sm + OFF_H1  + half * 4096;
    float* h2  = sm + OFF_H2  + half * 4352;
    float* ya  = sm + OFF_YA  + half * 2048;
    float* yb  = sm + OFF_YB  + half * 2048;
    float* agg = sm + OFF_AGG + half * 2048;
    float* zc  = sm + OFF_ZC  + half * 2048;
    float* s_wle1 = sm + OFF_WLE1;
    float* s_wle2 = sm + OFF_WLE2;
    float* s_wle3 = sm + OFF_WLE3;
    unsigned short* s_jl = (unsigned short*)(sm + SMEM_FLOATS);
    unsigned char*  s_ii = (unsigned char*)(s_jl + 1024);
    unsigned char*  s_jj = s_ii + 512;

    const int c0 = (ltid & 15) * 4;
    const int r0 = (ltid >> 4) * 2;

    // ---- shared staging (all 512 threads), then ONE global sync ----
    for (int p = tid; p < 512; p += NT) {
        if (p < 496) {
            int pp = p, i = 0;
            while (pp >= 31 - i) { pp -= 31 - i; i++; }
            s_ii[p] = (unsigned char)i;
            s_jj[p] = (unsigned char)(i + 1 + pp);
        } else {
            s_ii[p] = 0; s_jj[p] = 1;
        }
    }
    for (int idx = tid; idx < 1024; idx += NT) {
        int n = idx >> 5, k = idx & 31;
        s_jl[idx] = (k < n)
            ? (unsigned short)(k * 31 - ((k * (k - 1)) >> 1) + (n - k - 1))
            : (unsigned short)0xFFFF;
    }
    for (int idx = tid; idx < 8192; idx += NT) s_wle1[idx] = P.le1_w[idx];
    for (int idx = tid; idx < 4096; idx += NT) {
        s_wle2[idx] = P.le2_w[idx];
        s_wle3[idx] = P.le3_w[idx];
    }
    __syncthreads();   // the ONLY CTA-wide barrier; halves are independent after this

    const float* zb = P.z + (size_t)(2 * blockIdx.x + half) * (16 * 32 * 32);

    // ---- Phase A: ya/yb = src @ ee1_w (streamed; ee1_b folded into ya) ----
    {
        float accA0[4], accA1[4], accB0[4] = {0,0,0,0}, accB1[4] = {0,0,0,0};
#pragma unroll
        for (int j = 0; j < 4; j++) {
            float bv = P.ee1_b[c0 + j];
            accA0[j] = bv; accA1[j] = bv;
        }
#pragma unroll 1
        for (int ch = 0; ch < 8; ch++) {
            for (int idx = ltid; idx < 2048; idx += 256) {
                int o = idx >> 6, fl = idx & 63;
                int t = 2 * ch + (fl >> 5), e = fl & 31;
                int off = (t * 32 + o) * 32 + e;
                float v = zb[off];
                if (t > 0) v -= zb[off - 1024];
                h1[o * 64 + fl] = v;
            }
            bsync(barid);
            acc_chunk(h1, P.ee1_w + ch * 4096, accA0, accA1, r0, c0);
            acc_chunk(h1, P.ee1_w + 512 * 64 + ch * 4096, accB0, accB1, r0, c0);
            bsync(barid);
        }
#pragma unroll
        for (int j = 0; j < 4; j++) {
            ya[r0 * 64 + c0 + j] = accA0[j];
            ya[(r0 + 1) * 64 + c0 + j] = accA1[j];
            yb[r0 * 64 + c0 + j] = accB0[j];
            yb[(r0 + 1) * 64 + c0 + j] = accB1[j];
        }
    }
    bsync(barid);

    // ---- ee edge block (weights from global/L1) ----
    edge_block(ya, yb, P.ee2_w, P.ee2_b, P.ee3_w, P.ee3_b,
               h1, h2, yb, agg, s_ii, s_jj, s_jl, ltid, barid);

    // ---- ne MLP ----
    layer32x64<64, false, false>(agg, P.ne1_w + 512 * 64, P.ne1_b, ya, ltid);
    {
        float acc0[4], acc1[4];
#pragma unroll
        for (int j = 0; j < 4; j++) {
            acc0[j] = ya[r0 * 64 + c0 + j];          // own cells, no sync
            acc1[j] = ya[(r0 + 1) * 64 + c0 + j];
        }
#pragma unroll 1
        for (int ch = 0; ch < 8; ch++) {
            for (int idx = ltid; idx < 2048; idx += 256) {
                int o = idx >> 6, fl = idx & 63;
                int t = 2 * ch + (fl >> 5), e = fl & 31;
                int off = (t * 32 + o) * 32 + e;
                float v = zb[off];
                if (t > 0) v -= zb[off - 1024];
                h1[o * 64 + fl] = v;
            }
            bsync(barid);
            acc_chunk(h1, P.ne1_w + ch * 4096, acc0, acc1, r0, c0);
            bsync(barid);
        }
#pragma unroll
        for (int j = 0; j < 4; j++) {
            ya[r0 * 64 + c0 + j] = fmaxf(acc0[j], 0.f);
            ya[(r0 + 1) * 64 + c0 + j] = fmaxf(acc1[j], 0.f);
        }
    }
    bsync(barid);
    layer32x64<64, false, true>(ya, P.ne2_w, P.ne2_b, h1, ltid);
    bsync(barid);
    layer_small(h1, 64, P.ne3_w, P.ne3_b, h2, 32, true, ltid);
    bsync(barid);
    layer_small(h2, 32, P.ne4_w, P.ne4_b, h1, 32, false, ltid);   // z_impl
    bsync(barid);

    // zc = concat(z[b,-1], z_impl)
    const float* zlast = zb + 15 * 32 * 32;
    for (int idx = ltid; idx < 2048; idx += 256) {
        int o = idx >> 6, c = idx & 63;
        zc[idx] = (c < 32) ? zlast[o * 32 + c] : h1[o * 32 + (c - 32)];
    }
    bsync(barid);

    // ---- rollout ----
    const int ostride = P.t_future * 1024;
    float* outb = P.out + (size_t)(2 * blockIdx.x + half) * ostride;
#pragma unroll 1
    for (int t = 0; t < P.t_future; t++) {
        layer32x64<64, false, false>(zc, s_wle1,           P.le1_b, ya, ltid);
        layer32x64<64, false, false>(zc, s_wle1 + 64 * 64, nullptr, yb, ltid);
        bsync(barid);
        edge_block(ya, yb, s_wle2, P.le2_b, s_wle3, P.le3_b,
                   h1, h2, yb, agg, s_ii, s_jj, s_jl, ltid, barid);

        layer32x64<64, false, false>(zc,  P.lt1_w,           P.lt1_b, h1, ltid);
        layer32x64<64, true,  true >(agg, P.lt1_w + 64 * 64, nullptr, h1, ltid);
        bsync(barid);
        layer32x64<64, false, true>(h1, P.lt2_w, P.lt2_b, h2, ltid);
        bsync(barid);
        layer_small(h2, 64, P.lt3_w, P.lt3_b, h1, 32, true, ltid);
        bsync(barid);
        layer_small(h1, 32, P.lt4_w, P.lt4_b, h2, 16, true, ltid);
        bsync(barid);
        layer32x64<16, false, false>(h2, P.lt5_w, P.lt5_b, h1, ltid);   // delta
        bsync(barid);

        for (int idx = ltid; idx < 2048; idx += 256) {
            float zn = zc[idx] + h1[idx];
            zc[idx] = zn;
            int o = idx >> 6, c = idx & 63;
            if (c < 32) outb[t * 1024 + o * 32 + c] = zn;
        }
        bsync(barid);
    }
}

extern "C" void kernel_launch(void* const* d_in, const int* in_sizes, int n_in,
                              void* d_out, int out_size)
{
    Params P;
    int i = 0;
    P.z     = (const float*)d_in[i++];
    P.ee1_w = (const float*)d_in[i++]; P.ee1_b = (const float*)d_in[i++];
    P.ee2_w = (const float*)d_in[i++]; P.ee2_b = (const float*)d_in[i++];
    P.ee3_w = (const float*)d_in[i++]; P.ee3_b = (const float*)d_in[i++];
    P.ne1_w = (const float*)d_in[i++]; P.ne1_b = (const float*)d_in[i++];
    P.ne2_w = (const float*)d_in[i++]; P.ne2_b = (const float*)d_in[i++];
    P.ne3_w = (const float*)d_in[i++]; P.ne3_b = (const float*)d_in[i++];
    P.ne4_w = (const float*)d_in[i++]; P.ne4_b = (const float*)d_in[i++];
    P.le1_w = (const float*)d_in[i++]; P.le1_b = (const float*)d_in[i++];
    P.le2_w = (const float*)d_in[i++]; P.le2_b = (const float*)d_in[i++];
    P.le3_w = (const float*)d_in[i++]; P.le3_b = (const float*)d_in[i++];
    P.lt1_w = (const float*)d_in[i++]; P.lt1_b = (const float*)d_in[i++];
    P.lt2_w = (const float*)d_in[i++]; P.lt2_b = (const float*)d_in[i++];
    P.lt3_w = (const float*)d_in[i++]; P.lt3_b = (const float*)d_in[i++];
    P.lt4_w = (const float*)d_in[i++]; P.lt4_b = (const float*)d_in[i++];
    P.lt5_w = (const float*)d_in[i++]; P.lt5_b = (const float*)d_in[i++];
    P.out = (float*)d_out;
    P.t_future = out_size / (256 * 32 * 32);

    cudaFuncSetAttribute(RelationalLatentDynamics_82849919140105_kernel,
                         cudaFuncAttributeMaxDynamicSharedMemorySize, SMEM_BYTES);
    RelationalLatentDynamics_82849919140105_kernel<<<128, NT, SMEM_BYTES>>>(P);
}

// round 10
// speedup vs baseline: 1.0290x; 1.0290x over previous
#include <cuda_runtime.h>

#define NT 256

// B=256, T=16, O=32, E=32, I=32, H=HL=64, TE=512, EI=64, P=496
// One CTA = two batches, fused everywhere (shared W loads). grid=128, occ 1.
// Edge-block GEMM: fused 256-row (2 chunks x 2 batches), 8x8 tiles/thread.

struct Params {
    const float* z;
    const float *ee1_w,*ee1_b,*ee2_w,*ee2_b,*ee3_w,*ee3_b;
    const float *ne1_w,*ne1_b,*ne2_w,*ne2_b,*ne3_w,*ne3_b,*ne4_w,*ne4_b;
    const float *le1_w,*le1_b,*le2_w,*le2_b,*le3_w,*le3_b;
    const float *lt1_w,*lt1_b,*lt2_w,*lt2_b,*lt3_w,*lt3_b,*lt4_w,*lt4_b,*lt5_w,*lt5_b;
    float* out;
    int t_future;
};

__device__ __forceinline__ void fma4(float* acc, float a, const float4& w) {
    acc[0] = fmaf(a, w.x, acc[0]);
    acc[1] = fmaf(a, w.y, acc[1]);
    acc[2] = fmaf(a, w.z, acc[2]);
    acc[3] = fmaf(a, w.w, acc[3]);
}

// two-batch 32x64 layer: outX (opt +=) = inX[32][IN] @ W[IN][64] (+bias) (opt relu)
// 256 threads: 2 rows x 4 cols per thread per batch; W loads shared.
template<int IN, bool ACC, bool RELU>
__device__ __forceinline__ void layer2(const float* __restrict__ in0,
                                       const float* __restrict__ in1,
                                       const float* __restrict__ W,
                                       const float* __restrict__ bias,
                                       float* __restrict__ out0,
                                       float* __restrict__ out1, int tid)
{
    const int c0 = (tid & 15) * 4;
    const int r0 = (tid >> 4) * 2;
    float acc[2][2][4];
    if (ACC) {
#pragma unroll
        for (int i = 0; i < 2; i++)
#pragma unroll
            for (int j = 0; j < 4; j++) {
                acc[0][i][j] = out0[(r0 + i) * 64 + c0 + j];
                acc[1][i][j] = out1[(r0 + i) * 64 + c0 + j];
            }
    } else {
#pragma unroll
        for (int j = 0; j < 4; j++) {
            float bv = bias ? bias[c0 + j] : 0.f;
            acc[0][0][j] = bv; acc[0][1][j] = bv;
            acc[1][0][j] = bv; acc[1][1][j] = bv;
        }
    }
    const float* i00 = in0 + r0 * IN;
    const float* i01 = i00 + IN;
    const float* i10 = in1 + r0 * IN;
    const float* i11 = i10 + IN;
#pragma unroll 4
    for (int k = 0; k < IN; k += 4) {
        float4 w0 = *(const float4*)(W + (k + 0) * 64 + c0);
        float4 w1 = *(const float4*)(W + (k + 1) * 64 + c0);
        float4 w2 = *(const float4*)(W + (k + 2) * 64 + c0);
        float4 w3 = *(const float4*)(W + (k + 3) * 64 + c0);
        float4 a;
        a = *(const float4*)(i00 + k);
        fma4(acc[0][0], a.x, w0); fma4(acc[0][0], a.y, w1); fma4(acc[0][0], a.z, w2); fma4(acc[0][0], a.w, w3);
        a = *(const float4*)(i01 + k);
        fma4(acc[0][1], a.x, w0); fma4(acc[0][1], a.y, w1); fma4(acc[0][1], a.z, w2); fma4(acc[0][1], a.w, w3);
        a = *(const float4*)(i10 + k);
        fma4(acc[1][0], a.x, w0); fma4(acc[1][0], a.y, w1); fma4(acc[1][0], a.z, w2); fma4(acc[1][0], a.w, w3);
        a = *(const float4*)(i11 + k);
        fma4(acc[1][1], a.x, w0); fma4(acc[1][1], a.y, w1); fma4(acc[1][1], a.z, w2); fma4(acc[1][1], a.w, w3);
    }
#pragma unroll
    for (int i = 0; i < 2; i++)
#pragma unroll
        for (int j = 0; j < 4; j++) {
            float v0 = acc[0][i][j], v1 = acc[1][i][j];
            if (RELU) { v0 = fmaxf(v0, 0.f); v1 = fmaxf(v1, 0.f); }
            out0[(r0 + i) * 64 + c0 + j] = v0;
            out1[(r0 + i) * 64 + c0 + j] = v1;
        }
}

// fused edge GEMM: C(256x64, split per batch into h2 with stride 68)
//   = relu(A(256x64 fused h1) @ Ws(64x64 smem) + b2)
// 256 threads: 8 rows x 8 cols per thread.
__device__ __forceinline__ void gemm256(const float* __restrict__ A_,
                                        const float* __restrict__ Ws,
                                        const float* __restrict__ b2,
                                        float* __restrict__ h2, int tid)
{
    const int rg = tid >> 3;          // 0..31 -> rows rg*8..+7
    const int cg = (tid & 7) * 8;     // col base
    const float* A = A_ + rg * 8 * 64;
    float acc[8][8];
#pragma unroll
    for (int j = 0; j < 8; j++) {
        float bv = b2[cg + j];
#pragma unroll
        for (int i = 0; i < 8; i++) acc[i][j] = bv;
    }
#pragma unroll 2
    for (int k = 0; k < 64; k += 4) {
        float4 w0a = *(const float4*)(Ws + (k + 0) * 64 + cg);
        float4 w0b = *(const float4*)(Ws + (k + 0) * 64 + cg + 4);
        float4 w1a = *(const float4*)(Ws + (k + 1) * 64 + cg);
        float4 w1b = *(const float4*)(Ws + (k + 1) * 64 + cg + 4);
        float4 w2a = *(const float4*)(Ws + (k + 2) * 64 + cg);
        float4 w2b = *(const float4*)(Ws + (k + 2) * 64 + cg + 4);
        float4 w3a = *(const float4*)(Ws + (k + 3) * 64 + cg);
        float4 w3b = *(const float4*)(Ws + (k + 3) * 64 + cg + 4);
#pragma unroll
        for (int i = 0; i < 8; i++) {
            float4 a = *(const float4*)(A + i * 64 + k);
            fma4(acc[i],     a.x, w0a); fma4(acc[i] + 4, a.x, w0b);
            fma4(acc[i],     a.y, w1a); fma4(acc[i] + 4, a.y, w1b);
            fma4(acc[i],     a.z, w2a); fma4(acc[i] + 4, a.z, w2b);
            fma4(acc[i],     a.w, w3a); fma4(acc[i] + 4, a.w, w3b);
        }
    }
    const int b  = rg >> 4;           // batch
    const int pl = (rg & 15) * 8;     // local row within batch
    float* C = h2 + b * 8704 + pl * 68 + cg;
#pragma unroll
    for (int i = 0; i < 8; i++) {
        *(float4*)(C + i * 68) = make_float4(
            fmaxf(acc[i][0], 0.f), fmaxf(acc[i][1], 0.f),
            fmaxf(acc[i][2], 0.f), fmaxf(acc[i][3], 0.f));
        *(float4*)(C + i * 68 + 4) = make_float4(
            fmaxf(acc[i][4], 0.f), fmaxf(acc[i][5], 0.f),
            fmaxf(acc[i][6], 0.f), fmaxf(acc[i][7], 0.f));
    }
}

// two-batch agg: aggX[32][64] = GX[32][64] @ Ws3[64][64] + (31-2n)*b3
__device__ __forceinline__ void aggGemm_2(const float* __restrict__ G0,
                                          const float* __restrict__ G1,
                                          const float* __restrict__ Ws3,
                                          const float* __restrict__ b3,
                                          float* __restrict__ agg0,
                                          float* __restrict__ agg1, int tid)
{
    const int c0 = (tid & 15) * 4;
    const int r0 = (tid >> 4) * 2;
    const float sc0 = (float)(31 - 2 * r0);
    const float sc1 = (float)(31 - 2 * (r0 + 1));
    float acc[2][2][4];
#pragma unroll
    for (int j = 0; j < 4; j++) {
        float bv = b3[c0 + j];
        acc[0][0][j] = sc0 * bv; acc[0][1][j] = sc1 * bv;
        acc[1][0][j] = sc0 * bv; acc[1][1][j] = sc1 * bv;
    }
#pragma unroll 4
    for (int k = 0; k < 64; k += 4) {
        float4 w0 = *(const float4*)(Ws3 + (k + 0) * 64 + c0);
        float4 w1 = *(const float4*)(Ws3 + (k + 1) * 64 + c0);
        float4 w2 = *(const float4*)(Ws3 + (k + 2) * 64 + c0);
        float4 w3 = *(const float4*)(Ws3 + (k + 3) * 64 + c0);
        float4 a;
        a = *(const float4*)(G0 + r0 * 64 + k);
        fma4(acc[0][0], a.x, w0); fma4(acc[0][0], a.y, w1); fma4(acc[0][0], a.z, w2); fma4(acc[0][0], a.w, w3);
        a = *(const float4*)(G0 + (r0 + 1) * 64 + k);
        fma4(acc[0][1], a.x, w0); fma4(acc[0][1], a.y, w1); fma4(acc[0][1], a.z, w2); fma4(acc[0][1], a.w, w3);
        a = *(const float4*)(G1 + r0 * 64 + k);
        fma4(acc[1][0], a.x, w0); fma4(acc[1][0], a.y, w1); fma4(acc[1][0], a.z, w2); fma4(acc[1][0], a.w, w3);
        a = *(const float4*)(G1 + (r0 + 1) * 64 + k);
        fma4(acc[1][1], a.x, w0); fma4(acc[1][1], a.y, w1); fma4(acc[1][1], a.z, w2); fma4(acc[1][1], a.w, w3);
    }
#pragma unroll
    for (int i = 0; i < 2; i++)
#pragma unroll
        for (int j = 0; j < 4; j++) {
            agg0[(r0 + i) * 64 + c0 + j] = acc[0][i][j];
            agg1[(r0 + i) * 64 + c0 + j] = acc[1][i][j];
        }
}

// two-batch small layer: outX[32][OUT] = relu?(inX[32][IN] @ W + b); W loads shared
__device__ __forceinline__ void layer_small_2(const float* __restrict__ in0,
                                              const float* __restrict__ in1, int IN,
                                              const float* __restrict__ W,
                                              const float* __restrict__ bias,
                                              float* __restrict__ out0,
                                              float* __restrict__ out1, int OUT,
                                              bool relu, int tid)
{
    for (int idx = tid; idx < 32 * OUT; idx += NT) {
        int r = idx / OUT, c = idx % OUT;
        float a0 = bias[c], a1 = a0;
        const float* i0 = in0 + r * IN;
        const float* i1 = in1 + r * IN;
#pragma unroll 4
        for (int k = 0; k < IN; k++) {
            float w = W[k * OUT + c];
            a0 = fmaf(i0[k], w, a0);
            a1 = fmaf(i1[k], w, a1);
        }
        out0[idx] = relu ? fmaxf(a0, 0.f) : a0;
        out1[idx] = relu ? fmaxf(a1, 0.f) : a1;
    }
}

// two-batch streamed k-chunk accumulate: acc[bb][row][col] += sX[32][64] @ Wg[64][64]
__device__ __forceinline__ void acc_chunk2(const float* __restrict__ s0,
                                           const float* __restrict__ s1,
                                           const float* __restrict__ Wg,
                                           float acc[2][2][4], int r0, int c0)
{
    const float* a00 = s0 + r0 * 64;
    const float* a01 = a00 + 64;
    const float* a10 = s1 + r0 * 64;
    const float* a11 = a10 + 64;
#pragma unroll 4
    for (int k = 0; k < 64; k += 4) {
        float4 w0 = *(const float4*)(Wg + (k + 0) * 64 + c0);
        float4 w1 = *(const float4*)(Wg + (k + 1) * 64 + c0);
        float4 w2 = *(const float4*)(Wg + (k + 2) * 64 + c0);
        float4 w3 = *(const float4*)(Wg + (k + 3) * 64 + c0);
        float4 a;
        a = *(const float4*)(a00 + k);
        fma4(acc[0][0], a.x, w0); fma4(acc[0][0], a.y, w1); fma4(acc[0][0], a.z, w2); fma4(acc[0][0], a.w, w3);
        a = *(const float4*)(a01 + k);
        fma4(acc[0][1], a.x, w0); fma4(acc[0][1], a.y, w1); fma4(acc[0][1], a.z, w2); fma4(acc[0][1], a.w, w3);
        a = *(const float4*)(a10 + k);
        fma4(acc[1][0], a.x, w0); fma4(acc[1][0], a.y, w1); fma4(acc[1][0], a.z, w2); fma4(acc[1][0], a.w, w3);
        a = *(const float4*)(a11 + k);
        fma4(acc[1][1], a.x, w0); fma4(acc[1][1], a.y, w1); fma4(acc[1][1], a.z, w2); fma4(acc[1][1], a.w, w3);
    }
}

// fused two-batch edge block: ya/yb -> agg. b1 pre-folded into ya.
// 4 windows of (128 pairs x 2 batches) = 256-row fused GEMMs.
__device__ __forceinline__ void edge_block_f(const float* ya0, const float* ya1,
                                             const float* yb0, const float* yb1,
                                             const float* Ws2, const float* __restrict__ b2,
                                             const float* Ws3, const float* __restrict__ b3,
                                             float* h1, float* h2,
                                             float* Gs0, float* Gs1,
                                             float* agg0, float* agg1,
                                             const unsigned char* ii, const unsigned char* jj,
                                             const unsigned short* jl, int tid)
{
    const int n   = tid >> 3;          // 0..31 (node owned for scatter)
    const int c0s = (tid & 7) * 8;
    const int rs    = n * 31 - ((n * (n - 1)) >> 1);
    const int iiend = rs + 31 - n;
    float g[2][8];
#pragma unroll
    for (int j = 0; j < 8; j++) { g[0][j] = 0.f; g[1][j] = 0.f; }
    int kcur = 0;

#pragma unroll 1
    for (int ch = 0; ch < 4; ch++) {
        const int p0 = ch * 128;
        // h1 fused build: rows 0..127 = batch0 pairs, 128..255 = batch1 pairs
        for (int e = tid; e < 128 * 64; e += NT) {
            int pl = e >> 6, c = e & 63;
            int p = p0 + pl;
            int ia = ii[p] * 64 + c, ja = jj[p] * 64 + c;
            h1[e]            = fmaxf(ya0[ia] + yb0[ja], 0.f);
            h1[8192 + e]     = fmaxf(ya1[ia] + yb1[ja], 0.f);
        }
        __syncthreads();
        gemm256(h1, Ws2, b2, h2, tid);
        __syncthreads();
        // signed sparse scatter into register G (both batches)
        int lo = max(rs, p0), hi = min(iiend, p0 + 128);
        for (int p = lo; p < hi; p++) {
            const float* r0p = h2 + (p - p0) * 68 + c0s;
            const float* r1p = h2 + 8704 + (p - p0) * 68 + c0s;
            float4 u0 = *(const float4*)(r0p), u1 = *(const float4*)(r0p + 4);
            float4 v0 = *(const float4*)(r1p), v1 = *(const float4*)(r1p + 4);
            g[0][0] += u0.x; g[0][1] += u0.y; g[0][2] += u0.z; g[0][3] += u0.w;
            g[0][4] += u1.x; g[0][5] += u1.y; g[0][6] += u1.z; g[0][7] += u1.w;
            g[1][0] += v0.x; g[1][1] += v0.y; g[1][2] += v0.z; g[1][3] += v0.w;
            g[1][4] += v1.x; g[1][5] += v1.y; g[1][6] += v1.z; g[1][7] += v1.w;
        }
        while (kcur < n) {
            int p = jl[(n << 5) + kcur];
            if (p >= p0 + 128) break;
            const float* r0p = h2 + (p - p0) * 68 + c0s;
            const float* r1p = h2 + 8704 + (p - p0) * 68 + c0s;
            float4 u0 = *(const float4*)(r0p), u1 = *(const float4*)(r0p + 4);
            float4 v0 = *(const float4*)(r1p), v1 = *(const float4*)(r1p + 4);
            g[0][0] -= u0.x; g[0][1] -= u0.y; g[0][2] -= u0.z; g[0][3] -= u0.w;
            g[0][4] -= u1.x; g[0][5] -= u1.y; g[0][6] -= u1.z; g[0][7] -= u1.w;
            g[1][0] -= v0.x; g[1][1] -= v0.y; g[1][2] -= v0.z; g[1][3] -= v0.w;
            g[1][4] -= v1.x; g[1][5] -= v1.y; g[1][6] -= v1.z; g[1][7] -= v1.w;
            kcur++;
        }
        // NOTE: next window's h1-build + its sync also orders scatter before next gemm.
        __syncthreads();
    }
#pragma unroll
    for (int j = 0; j < 8; j++) {
        Gs0[n * 64 + c0s + j] = g[0][j];
        Gs1[n * 64 + c0s + j] = g[1][j];
    }
    __syncthreads();
    aggGemm_2(Gs0, Gs1, Ws3, b3, agg0, agg1, tid);
    __syncthreads();
}

// smem layout (float offsets)
#define OFF_H1   0        // 2 x 128*64 (fused A; also reused as chunk/temp buffers)
#define OFF_H2   16384    // 2 x 128*68 (gemm out; agg aliased at batch bases)
#define OFF_YA   33792    // 2 x 2048
#define OFF_YB   37888
#define OFF_ZC   41984
#define OFF_W2   46080    // 64*64 staged (ee2 -> le2)
#define OFF_W3   50176    // 64*64 staged (ee3 -> le3)
#define SMEM_FLOATS 54272
#define SMEM_BYTES  (SMEM_FLOATS * 4 + 2048 + 1024)

__global__ void __launch_bounds__(NT, 1)
RelationalLatentDynamics_82849919140105_kernel(Params P)
{
    extern __shared__ float sm[];
    float* h1   = sm + OFF_H1;
    float* h1_0 = h1;                 // 32x64 temp (batch0)
    float* h1_1 = h1 + 8192;          // 32x64 temp (batch1)
    float* h2   = sm + OFF_H2;
    float* agg0 = h2;                 // aliased: agg lives at h2 batch bases
    float* agg1 = h2 + 8704;
    float* ya0  = sm + OFF_YA;        float* ya1 = ya0 + 2048;
    float* yb0  = sm + OFF_YB;        float* yb1 = yb0 + 2048;
    float* zc0  = sm + OFF_ZC;        float* zc1 = zc0 + 2048;
    float* s_w2 = sm + OFF_W2;
    float* s_w3 = sm + OFF_W3;
    unsigned short* s_jl = (unsigned short*)(sm + SMEM_FLOATS);
    unsigned char*  s_ii = (unsigned char*)(s_jl + 1024);
    unsigned char*  s_jj = s_ii + 512;

    const int tid = threadIdx.x;
    const int c0 = (tid & 15) * 4;
    const int r0 = (tid >> 4) * 2;

    // pair index tables (padded to 512)
    for (int p = tid; p < 512; p += NT) {
        if (p < 496) {
            int pp = p, i = 0;
            while (pp >= 31 - i) { pp -= 31 - i; i++; }
            s_ii[p] = (unsigned char)i;
            s_jj[p] = (unsigned char)(i + 1 + pp);
        } else {
            s_ii[p] = 0; s_jj[p] = 1;
        }
    }
    for (int idx = tid; idx < 1024; idx += NT) {
        int n = idx >> 5, k = idx & 31;
        s_jl[idx] = (k < n)
            ? (unsigned short)(k * 31 - ((k * (k - 1)) >> 1) + (n - k - 1))
            : (unsigned short)0xFFFF;
    }
    // stage ee2/ee3 weights
    for (int idx = tid; idx < 4096; idx += NT) {
        s_w2[idx] = P.ee2_w[idx];
        s_w3[idx] = P.ee3_w[idx];
    }

    const float* zb0 = P.z + (size_t)(2 * blockIdx.x) * (16 * 32 * 32);
    const float* zb1 = zb0 + 16 * 32 * 32;
    __syncthreads();

    // ---- Phase A: yaX/ybX = srcX @ ee1_w (streamed, ee1_b folded into ya) ----
    {
        float accA[2][2][4], accB[2][2][4];
#pragma unroll
        for (int j = 0; j < 4; j++) {
            float bv = P.ee1_b[c0 + j];
            accA[0][0][j] = bv; accA[0][1][j] = bv; accA[1][0][j] = bv; accA[1][1][j] = bv;
            accB[0][0][j] = 0.f; accB[0][1][j] = 0.f; accB[1][0][j] = 0.f; accB[1][1][j] = 0.f;
        }
#pragma unroll 1
        for (int ch = 0; ch < 8; ch++) {
            for (int idx = tid; idx < 2048; idx += NT) {
                int o = idx >> 6, fl = idx & 63;
                int t = 2 * ch + (fl >> 5), e = fl & 31;
                int off = (t * 32 + o) * 32 + e;
                float v0 = zb0[off], v1 = zb1[off];
                if (t > 0) {
                    int om = off - 1024;
                    v0 -= zb0[om]; v1 -= zb1[om];
                }
                h1_0[o * 64 + fl] = v0;
                h1_1[o * 64 + fl] = v1;
            }
            __syncthreads();
            acc_chunk2(h1_0, h1_1, P.ee1_w + ch * 4096, accA, r0, c0);
            acc_chunk2(h1_0, h1_1, P.ee1_w + 512 * 64 + ch * 4096, accB, r0, c0);
            __syncthreads();
        }
#pragma unroll
        for (int i = 0; i < 2; i++)
#pragma unroll
            for (int j = 0; j < 4; j++) {
                ya0[(r0 + i) * 64 + c0 + j] = accA[0][i][j];
                ya1[(r0 + i) * 64 + c0 + j] = accA[1][i][j];
                yb0[(r0 + i) * 64 + c0 + j] = accB[0][i][j];
                yb1[(r0 + i) * 64 + c0 + j] = accB[1][i][j];
            }
    }
    __syncthreads();

    // ---- ee edge block ----
    edge_block_f(ya0, ya1, yb0, yb1, s_w2, P.ee2_b, s_w3, P.ee3_b,
                 h1, h2, yb0, yb1, agg0, agg1, s_ii, s_jj, s_jl, tid);

    // ---- ne MLP ----
    layer2<64, false, false>(agg0, agg1, P.ne1_w + 512 * 64, P.ne1_b, ya0, ya1, tid);
    {
        float acc[2][2][4];
#pragma unroll
        for (int i = 0; i < 2; i++)
#pragma unroll
            for (int j = 0; j < 4; j++) {
                acc[0][i][j] = ya0[(r0 + i) * 64 + c0 + j];   // own cells
                acc[1][i][j] = ya1[(r0 + i) * 64 + c0 + j];
            }
#pragma unroll 1
        for (int ch = 0; ch < 8; ch++) {
            for (int idx = tid; idx < 2048; idx += NT) {
                int o = idx >> 6, fl = idx & 63;
                int t = 2 * ch + (fl >> 5), e = fl & 31;
                int off = (t * 32 + o) * 32 + e;
                float v0 = zb0[off], v1 = zb1[off];
                if (t > 0) {
                    int om = off - 1024;
                    v0 -= zb0[om]; v1 -= zb1[om];
                }
                h1_0[o * 64 + fl] = v0;
                h1_1[o * 64 + fl] = v1;
            }
            __syncthreads();
            acc_chunk2(h1_0, h1_1, P.ne1_w + ch * 4096, acc, r0, c0);
            __syncthreads();
        }
#pragma unroll
        for (int i = 0; i < 2; i++)
#pragma unroll
            for (int j = 0; j < 4; j++) {
                ya0[(r0 + i) * 64 + c0 + j] = fmaxf(acc[0][i][j], 0.f);
                ya1[(r0 + i) * 64 + c0 + j] = fmaxf(acc[1][i][j], 0.f);
            }
    }
    __syncthreads();
    layer2<64, false, true>(ya0, ya1, P.ne2_w, P.ne2_b, h1_0, h1_1, tid);
    __syncthreads();
    layer_small_2(h1_0, h1_1, 64, P.ne3_w, P.ne3_b, agg0, agg1, 32, true, tid);
    __syncthreads();
    layer_small_2(agg0, agg1, 32, P.ne4_w, P.ne4_b, h1_0, h1_1, 32, false, tid);  // z_impl
    __syncthreads();

    // zc = concat(z[b,-1], z_impl); restage w2/w3 with le weights
    const float* zl0 = zb0 + 15 * 32 * 32;
    const float* zl1 = zb1 + 15 * 32 * 32;
    for (int idx = tid; idx < 2048; idx += NT) {
        int o = idx >> 6, c = idx & 63;
        zc0[idx] = (c < 32) ? zl0[o * 32 + c] : h1_0[o * 32 + (c - 32)];
        zc1[idx] = (c < 32) ? zl1[o * 32 + c] : h1_1[o * 32 + (c - 32)];
    }
    for (int idx = tid; idx < 4096; idx += NT) {
        s_w2[idx] = P.le2_w[idx];
        s_w3[idx] = P.le3_w[idx];
    }
    __syncthreads();

    // ---- rollout ----
    const int ostride = P.t_future * 1024;
    float* out0 = P.out + (size_t)(2 * blockIdx.x) * ostride;
    float* out1 = out0 + ostride;
#pragma unroll 1
    for (int t = 0; t < P.t_future; t++) {
        layer2<64, false, false>(zc0, zc1, P.le1_w,           P.le1_b, ya0, ya1, tid);
        layer2<64, false, false>(zc0, zc1, P.le1_w + 64 * 64, nullptr, yb0, yb1, tid);
        __syncthreads();
        edge_block_f(ya0, ya1, yb0, yb1, s_w2, P.le2_b, s_w3, P.le3_b,
                     h1, h2, yb0, yb1, agg0, agg1, s_ii, s_jj, s_jl, tid);

        layer2<64, false, false>(zc0, zc1, P.lt1_w,            P.lt1_b, h1_0, h1_1, tid);
        layer2<64, true,  true >(agg0, agg1, P.lt1_w + 64 * 64, nullptr, h1_0, h1_1, tid);
        __syncthreads();
        layer2<64, false, true>(h1_0, h1_1, P.lt2_w, P.lt2_b, agg0, agg1, tid);
        __syncthreads();
        layer_small_2(agg0, agg1, 64, P.lt3_w, P.lt3_b, h1_0, h1_1, 32, true, tid);
        __syncthreads();
        layer_small_2(h1_0, h1_1, 32, P.lt4_w, P.lt4_b, agg0, agg1, 16, true, tid);
        __syncthreads();
        layer2<16, false, false>(agg0, agg1, P.lt5_w, P.lt5_b, h1_0, h1_1, tid);  // delta
        __syncthreads();

        for (int idx = tid; idx < 2048; idx += NT) {
            float zn0 = zc0[idx] + h1_0[idx];
            float zn1 = zc1[idx] + h1_1[idx];
            zc0[idx] = zn0; zc1[idx] = zn1;
            int o = idx >> 6, c = idx & 63;
            if (c < 32) {
                out0[t * 1024 + o * 32 + c] = zn0;
                out1[t * 1024 + o * 32 + c] = zn1;
            }
        }
        __syncthreads();
    }
}

extern "C" void kernel_launch(void* const* d_in, const int* in_sizes, int n_in,
                              void* d_out, int out_size)
{
    Params P;
    int i = 0;
    P.z     = (const float*)d_in[i++];
    P.ee1_w = (const float*)d_in[i++]; P.ee1_b = (const float*)d_in[i++];
    P.ee2_w = (const float*)d_in[i++]; P.ee2_b = (const float*)d_in[i++];
    P.ee3_w = (const float*)d_in[i++]; P.ee3_b = (const float*)d_in[i++];
    P.ne1_w = (const float*)d_in[i++]; P.ne1_b = (const float*)d_in[i++];
    P.ne2_w = (const float*)d_in[i++]; P.ne2_b = (const float*)d_in[i++];
    P.ne3_w = (const float*)d_in[i++]; P.ne3_b = (const float*)d_in[i++];
    P.ne4_w = (const float*)d_in[i++]; P.ne4_b = (const float*)d_in[i++];
    P.le1_w = (const float*)d_in[i++]; P.le1_b = (const float*)d_in[i++];
    P.le2_w = (const float*)d_in[i++]; P.le2_b = (const float*)d_in[i++];
    P.le3_w = (const float*)d_in[i++]; P.le3_b = (const float*)d_in[i++];
    P.lt1_w = (const float*)d_in[i++]; P.lt1_b = (const float*)d_in[i++];
    P.lt2_w = (const float*)d_in[i++]; P.lt2_b = (const float*)d_in[i++];
    P.lt3_w = (const float*)d_in[i++]; P.lt3_b = (const float*)d_in[i++];
    P.lt4_w = (const float*)d_in[i++]; P.lt4_b = (const float*)d_in[i++];
    P.lt5_w = (const float*)d_in[i++]; P.lt5_b = (const float*)d_in[i++];
    P.out = (float*)d_out;
    P.t_future = out_size / (256 * 32 * 32);

    cudaFuncSetAttribute(RelationalLatentDynamics_82849919140105_kernel,
                         cudaFuncAttributeMaxDynamicSharedMemorySize, SMEM_BYTES);
    RelationalLatentDynamics_82849919140105_kernel<<<128, NT, SMEM_BYTES>>>(P);
}

// round 12
// speedup vs baseline: 1.4564x; 1.4153x over previous
#include <cuda_runtime.h>
#include <cuda_bf16.h>

#define NT 256

// B=256, T=16, O=32, E=32, I=32, H=HL=64, TE=512, EI=64, P=496
// grid=128, 2 batches/CTA. Edge L2 GEMM on HMMA mma.sync m16n8k16 bf16 (3-term split).

struct Params {
    const float* z;
    const float *ee1_w,*ee1_b,*ee2_w,*ee2_b,*ee3_w,*ee3_b;
    const float *ne1_w,*ne1_b,*ne2_w,*ne2_b,*ne3_w,*ne3_b,*ne4_w,*ne4_b;
    const float *le1_w,*le1_b,*le2_w,*le2_b,*le3_w,*le3_b;
    const float *lt1_w,*lt1_b,*lt2_w,*lt2_b,*lt3_w,*lt3_b,*lt4_w,*lt4_b,*lt5_w,*lt5_b;
    float* out;
    int t_future;
};

// ---- smem layout (byte offsets) ----
#define SM_H2    0        // 512*68*4 = 139264 (also scratch region, see float aliases)
#define SM_BTH   139264   // ushort[64*72] = 9216
#define SM_BTL   148480   // 9216
#define SM_ACT   157696   // ya0,ya1,yb0,yb1 (32*66 fl each) + zc0,zc1 (2048 fl each)
#define SM_JL    207872   // 1024 u16
#define SM_II    209920   // 512 u8
#define SM_JJ    210432   // 512 u8
#define SM_B2    210944   // 64 floats
#define SMEM_BYTES 211200

#define YAP 66   // ya/yb pitch (bank-conflict relief on fragment gather)
#define H2P 68   // h2 pitch

__device__ __forceinline__ void fma4(float* acc, float a, const float4& w) {
    acc[0] = fmaf(a, w.x, acc[0]);
    acc[1] = fmaf(a, w.y, acc[1]);
    acc[2] = fmaf(a, w.z, acc[2]);
    acc[3] = fmaf(a, w.w, acc[3]);
}

// ---- HMMA primitives ----
__device__ __forceinline__ void mma16816(float* d, const unsigned* a, unsigned b0, unsigned b1) {
    asm volatile(
        "mma.sync.aligned.m16n8k16.row.col.f32.bf16.bf16.f32 "
        "{%0,%1,%2,%3}, {%4,%5,%6,%7}, {%8,%9}, {%0,%1,%2,%3};"
        : "+f"(d[0]), "+f"(d[1]), "+f"(d[2]), "+f"(d[3])
        : "r"(a[0]), "r"(a[1]), "r"(a[2]), "r"(a[3]), "r"(b0), "r"(b1));
}
// relu(ya+yb) for 2 consecutive cols -> packed bf16 hi (trunc) + lo (round)
__device__ __forceinline__ void build_pair(const float* pa, const float* pb, int c,
                                           unsigned& hi, unsigned& lo) {
    float2 va = *(const float2*)(pa + c);
    float2 vb = *(const float2*)(pb + c);
    float v0 = fmaxf(va.x + vb.x, 0.f);
    float v1 = fmaxf(va.y + vb.y, 0.f);
    unsigned u0 = __float_as_uint(v0), u1 = __float_as_uint(v1);
    asm("prmt.b32 %0, %1, %2, 0x7632;" : "=r"(hi) : "r"(u0), "r"(u1));
    float h0 = __uint_as_float(u0 & 0xFFFF0000u);
    float h1 = __uint_as_float(u1 & 0xFFFF0000u);
    asm("cvt.rn.bf16x2.f32 %0, %1, %2;" : "=r"(lo) : "f"(v1 - h1), "f"(v0 - h0));
}

// ---- scalar building blocks (R6 heritage) ----
template<int IN, bool ACC, bool RELU, int OP>
__device__ __forceinline__ void layer2(const float* __restrict__ in0,
                                       const float* __restrict__ in1,
                                       const float* __restrict__ W,
                                       const float* __restrict__ bias,
                                       float* __restrict__ out0,
                                       float* __restrict__ out1, int tid)
{
    const int c0 = (tid & 15) * 4;
    const int r0 = (tid >> 4) * 2;
    float acc[2][2][4];
    if (ACC) {
#pragma unroll
        for (int i = 0; i < 2; i++)
#pragma unroll
            for (int j = 0; j < 4; j++) {
                acc[0][i][j] = out0[(r0 + i) * OP + c0 + j];
                acc[1][i][j] = out1[(r0 + i) * OP + c0 + j];
            }
    } else {
#pragma unroll
        for (int j = 0; j < 4; j++) {
            float bv = bias ? bias[c0 + j] : 0.f;
            acc[0][0][j] = bv; acc[0][1][j] = bv;
            acc[1][0][j] = bv; acc[1][1][j] = bv;
        }
    }
    const float* i00 = in0 + r0 * IN;
    const float* i01 = i00 + IN;
    const float* i10 = in1 + r0 * IN;
    const float* i11 = i10 + IN;
#pragma unroll 4
    for (int k = 0; k < IN; k += 4) {
        float4 w0 = *(const float4*)(W + (k + 0) * 64 + c0);
        float4 w1 = *(const float4*)(W + (k + 1) * 64 + c0);
        float4 w2 = *(const float4*)(W + (k + 2) * 64 + c0);
        float4 w3 = *(const float4*)(W + (k + 3) * 64 + c0);
        float4 a;
        a = *(const float4*)(i00 + k);
        fma4(acc[0][0], a.x, w0); fma4(acc[0][0], a.y, w1); fma4(acc[0][0], a.z, w2); fma4(acc[0][0], a.w, w3);
        a = *(const float4*)(i01 + k);
        fma4(acc[0][1], a.x, w0); fma4(acc[0][1], a.y, w1); fma4(acc[0][1], a.z, w2); fma4(acc[0][1], a.w, w3);
        a = *(const float4*)(i10 + k);
        fma4(acc[1][0], a.x, w0); fma4(acc[1][0], a.y, w1); fma4(acc[1][0], a.z, w2); fma4(acc[1][0], a.w, w3);
        a = *(const float4*)(i11 + k);
        fma4(acc[1][1], a.x, w0); fma4(acc[1][1], a.y, w1); fma4(acc[1][1], a.z, w2); fma4(acc[1][1], a.w, w3);
    }
#pragma unroll
    for (int i = 0; i < 2; i++)
#pragma unroll
        for (int j = 0; j < 4; j++) {
            float v0 = acc[0][i][j], v1 = acc[1][i][j];
            if (RELU) { v0 = fmaxf(v0, 0.f); v1 = fmaxf(v1, 0.f); }
            out0[(r0 + i) * OP + c0 + j] = v0;
            out1[(r0 + i) * OP + c0 + j] = v1;
        }
}

__device__ __forceinline__ void aggGemm_2(const float* __restrict__ G0,
                                          const float* __restrict__ G1,
                                          const float* __restrict__ W3,
                                          const float* __restrict__ b3,
                                          float* __restrict__ agg0,
                                          float* __restrict__ agg1, int tid)
{
    const int c0 = (tid & 15) * 4;
    const int r0 = (tid >> 4) * 2;
    const float sc0 = (float)(31 - 2 * r0);
    const float sc1 = (float)(31 - 2 * (r0 + 1));
    float acc[2][2][4];
#pragma unroll
    for (int j = 0; j < 4; j++) {
        float bv = b3[c0 + j];
        acc[0][0][j] = sc0 * bv; acc[0][1][j] = sc1 * bv;
        acc[1][0][j] = sc0 * bv; acc[1][1][j] = sc1 * bv;
    }
#pragma unroll 4
    for (int k = 0; k < 64; k += 4) {
        float4 w0 = *(const float4*)(W3 + (k + 0) * 64 + c0);
        float4 w1 = *(const float4*)(W3 + (k + 1) * 64 + c0);
        float4 w2 = *(const float4*)(W3 + (k + 2) * 64 + c0);
        float4 w3 = *(const float4*)(W3 + (k + 3) * 64 + c0);
        float4 a;
        a = *(const float4*)(G0 + r0 * 64 + k);
        fma4(acc[0][0], a.x, w0); fma4(acc[0][0], a.y, w1); fma4(acc[0][0], a.z, w2); fma4(acc[0][0], a.w, w3);
        a = *(const float4*)(G0 + (r0 + 1) * 64 + k);
        fma4(acc[0][1], a.x, w0); fma4(acc[0][1], a.y, w1); fma4(acc[0][1], a.z, w2); fma4(acc[0][1], a.w, w3);
        a = *(const float4*)(G1 + r0 * 64 + k);
        fma4(acc[1][0], a.x, w0); fma4(acc[1][0], a.y, w1); fma4(acc[1][0], a.z, w2); fma4(acc[1][0], a.w, w3);
        a = *(const float4*)(G1 + (r0 + 1) * 64 + k);
        fma4(acc[1][1], a.x, w0); fma4(acc[1][1], a.y, w1); fma4(acc[1][1], a.z, w2); fma4(acc[1][1], a.w, w3);
    }
#pragma unroll
    for (int i = 0; i < 2; i++)
#pragma unroll
        for (int j = 0; j < 4; j++) {
            agg0[(r0 + i) * 64 + c0 + j] = acc[0][i][j];
            agg1[(r0 + i) * 64 + c0 + j] = acc[1][i][j];
        }
}

__device__ __forceinline__ void layer_small_2(const float* __restrict__ in0,
                                              const float* __restrict__ in1, int IN,
                                              const float* __restrict__ W,
                                              const float* __restrict__ bias,
                                              float* __restrict__ out0,
                                              float* __restrict__ out1, int OUT,
                                              bool relu, int tid)
{
    for (int idx = tid; idx < 32 * OUT; idx += NT) {
        int r = idx / OUT, c = idx % OUT;
        float a0 = bias[c], a1 = a0;
        const float* i0 = in0 + r * IN;
        const float* i1 = in1 + r * IN;
#pragma unroll 4
        for (int k = 0; k < IN; k++) {
            float w = W[k * OUT + c];
            a0 = fmaf(i0[k], w, a0);
            a1 = fmaf(i1[k], w, a1);
        }
        out0[idx] = relu ? fmaxf(a0, 0.f) : a0;
        out1[idx] = relu ? fmaxf(a1, 0.f) : a1;
    }
}

__device__ __forceinline__ void acc_chunk2(const float* __restrict__ s0,
                                           const float* __restrict__ s1,
                                           const float* __restrict__ Wg,
                                           float acc[2][2][4], int r0, int c0)
{
    const float* a00 = s0 + r0 * 64;
    const float* a01 = a00 + 64;
    const float* a10 = s1 + r0 * 64;
    const float* a11 = a10 + 64;
#pragma unroll 4
    for (int k = 0; k < 64; k += 4) {
        float4 w0 = *(const float4*)(Wg + (k + 0) * 64 + c0);
        float4 w1 = *(const float4*)(Wg + (k + 1) * 64 + c0);
        float4 w2 = *(const float4*)(Wg + (k + 2) * 64 + c0);
        float4 w3 = *(const float4*)(Wg + (k + 3) * 64 + c0);
        float4 a;
        a = *(const float4*)(a00 + k);
        fma4(acc[0][0], a.x, w0); fma4(acc[0][0], a.y, w1); fma4(acc[0][0], a.z, w2); fma4(acc[0][0], a.w, w3);
        a = *(const float4*)(a01 + k);
        fma4(acc[0][1], a.x, w0); fma4(acc[0][1], a.y, w1); fma4(acc[0][1], a.z, w2); fma4(acc[0][1], a.w, w3);
        a = *(const float4*)(a10 + k);
        fma4(acc[1][0], a.x, w0); fma4(acc[1][0], a.y, w1); fma4(acc[1][0], a.z, w2); fma4(acc[1][0], a.w, w3);
        a = *(const float4*)(a11 + k);
        fma4(acc[1][1], a.x, w0); fma4(acc[1][1], a.y, w1); fma4(acc[1][1], a.z, w2); fma4(acc[1][1], a.w, w3);
    }
}

// stage Bt[n][k] = W2[k][n] as bf16 hi(trunc)/lo(round), pitch 72
__device__ __forceinline__ void stage_Bt(const float* __restrict__ W2g,
                                         unsigned short* Bth, unsigned short* Btl, int tid)
{
    for (int idx = tid; idx < 4096; idx += NT) {
        int n = idx >> 6, k = idx & 63;
        float w = W2g[k * 64 + n];
        unsigned u = __float_as_uint(w);
        unsigned short hb = (unsigned short)(u >> 16);
        float hf = __uint_as_float(u & 0xFFFF0000u);
        __nv_bfloat16 lb = __float2bfloat16(w - hf);
        Bth[n * 72 + k] = hb;
        Btl[n * 72 + k] = *(unsigned short*)&lb;
    }
}

// per-warp HMMA GEMM for one batch: h2[512][H2P] = relu(relu(ya[ii]+yb[jj]) @ W2 + b2)
__device__ __forceinline__ void edge_gemm_mma(const float* __restrict__ ya,   // pitch YAP, b1 folded
                                              const float* __restrict__ yb,
                                              const unsigned short* __restrict__ Bth,
                                              const unsigned short* __restrict__ Btl,
                                              const float* __restrict__ b2s,
                                              float* __restrict__ h2f,
                                              const unsigned char* __restrict__ ii,
                                              const unsigned char* __restrict__ jj,
                                              int tid)
{
    const int wid = tid >> 5, lane = tid & 31;
    const int g = lane >> 2, t = lane & 3;
#pragma unroll 1
    for (int mt = 0; mt < 4; mt++) {
        const int tb = (wid * 4 + mt) * 16;
        const int r0 = tb + g, r1 = r0 + 8;
        const float* pa0 = ya + ii[r0] * YAP;
        const float* pb0 = yb + jj[r0] * YAP;
        const float* pa1 = ya + ii[r1] * YAP;
        const float* pb1 = yb + jj[r1] * YAP;
        unsigned Ahi[4][4], Alo[4][4];
#pragma unroll
        for (int ks = 0; ks < 4; ks++) {
            int c = ks * 16 + 2 * t;
            build_pair(pa0, pb0, c,     Ahi[ks][0], Alo[ks][0]);
            build_pair(pa1, pb1, c,     Ahi[ks][1], Alo[ks][1]);
            build_pair(pa0, pb0, c + 8, Ahi[ks][2], Alo[ks][2]);
            build_pair(pa1, pb1, c + 8, Ahi[ks][3], Alo[ks][3]);
        }
#pragma unroll
        for (int ns = 0; ns < 8; ns++) {
            const int n = ns * 8 + g;
            const unsigned short* bh = Bth + n * 72;
            const unsigned short* bl = Btl + n * 72;
            float da[4] = {0,0,0,0}, db[4] = {0,0,0,0}, dc[4] = {0,0,0,0};
#pragma unroll
            for (int ks = 0; ks < 4; ks++) {
                int kb = ks * 16 + 2 * t;
                unsigned bh0 = *(const unsigned*)(bh + kb);
                unsigned bh1 = *(const unsigned*)(bh + kb + 8);
                unsigned bl0 = *(const unsigned*)(bl + kb);
                unsigned bl1 = *(const unsigned*)(bl + kb + 8);
                mma16816(da, Ahi[ks], bh0, bh1);
                mma16816(db, Ahi[ks], bl0, bl1);
                mma16816(dc, Alo[ks], bh0, bh1);
            }
            int col = ns * 8 + 2 * t;
            float b0v = b2s[col], b1v = b2s[col + 1];
            float2 o0, o1;
            o0.x = fmaxf(da[0] + db[0] + dc[0] + b0v, 0.f);
            o0.y = fmaxf(da[1] + db[1] + dc[1] + b1v, 0.f);
            o1.x = fmaxf(da[2] + db[2] + dc[2] + b0v, 0.f);
            o1.y = fmaxf(da[3] + db[3] + dc[3] + b1v, 0.f);
            *(float2*)(h2f + r0 * H2P + col) = o0;
            *(float2*)(h2f + r1 * H2P + col) = o1;
        }
    }
}

// full edge block: 2 batches -> agg0/agg1
__device__ void edge_full(const float* ya0, const float* ya1,
                          const float* yb0, const float* yb1,
                          const unsigned short* Bth, const unsigned short* Btl,
                          const float* b2s,
                          const float* __restrict__ W3g, const float* __restrict__ b3g,
                          float* h2f, float* Gs0, float* Gs1,
                          float* agg0, float* agg1,
                          const unsigned char* ii, const unsigned char* jj,
                          const unsigned short* jl, int tid)
{
    const int n = tid >> 3, c0s = (tid & 7) * 8;
    const int rs = n * 31 - ((n * (n - 1)) >> 1);
    const int iiend = rs + 31 - n;
    float g2[2][8];
#pragma unroll
    for (int j = 0; j < 8; j++) { g2[0][j] = 0.f; g2[1][j] = 0.f; }

#pragma unroll 1
    for (int b = 0; b < 2; b++) {
        edge_gemm_mma(b ? ya1 : ya0, b ? yb1 : yb0, Bth, Btl, b2s, h2f, ii, jj, tid);
        __syncthreads();
        float* g = g2[b];
        for (int p = rs; p < iiend; p++) {
            const float* r = h2f + p * H2P + c0s;
            float4 v0 = *(const float4*)r, v1 = *(const float4*)(r + 4);
            g[0] += v0.x; g[1] += v0.y; g[2] += v0.z; g[3] += v0.w;
            g[4] += v1.x; g[5] += v1.y; g[6] += v1.z; g[7] += v1.w;
        }
        for (int k = 0; k < n; k++) {
            int p = jl[(n << 5) + k];
            const float* r = h2f + p * H2P + c0s;
            float4 v0 = *(const float4*)r, v1 = *(const float4*)(r + 4);
            g[0] -= v0.x; g[1] -= v0.y; g[2] -= v0.z; g[3] -= v0.w;
            g[4] -= v1.x; g[5] -= v1.y; g[6] -= v1.z; g[7] -= v1.w;
        }
        __syncthreads();
    }
#pragma unroll
    for (int j = 0; j < 8; j++) {
        Gs0[n * 64 + c0s + j] = g2[0][j];
        Gs1[n * 64 + c0s + j] = g2[1][j];
    }
    __syncthreads();
    aggGemm_2(Gs0, Gs1, W3g, b3g, agg0, agg1, tid);
    __syncthreads();
}

__global__ void __launch_bounds__(NT, 1)
RelationalLatentDynamics_82849919140105_kernel(Params P)
{
    extern __shared__ char smb[];
    float* h2f = (float*)(smb + SM_H2);
    // scratch aliases inside h2 region
    float* sc0  = h2f;            // 4096 fl
    float* sc1  = h2f + 4096;
    float* t0   = h2f + 8192;     // 2048 fl
    float* t1   = h2f + 10240;
    float* Gs0  = h2f + 12288;
    float* Gs1  = h2f + 14336;
    float* agg0 = h2f + 16384;
    float* agg1 = h2f + 18432;
    unsigned short* Bth = (unsigned short*)(smb + SM_BTH);
    unsigned short* Btl = (unsigned short*)(smb + SM_BTL);
    float* act = (float*)(smb + SM_ACT);
    float* ya0 = act;              float* ya1 = act + 2112;
    float* yb0 = act + 4224;       float* yb1 = act + 6336;
    float* zc0 = act + 8448;       float* zc1 = act + 10496;
    unsigned short* s_jl = (unsigned short*)(smb + SM_JL);
    unsigned char*  s_ii = (unsigned char*)(smb + SM_II);
    unsigned char*  s_jj = (unsigned char*)(smb + SM_JJ);
    float* b2s = (float*)(smb + SM_B2);

    const int tid = threadIdx.x;
    const int c0 = (tid & 15) * 4;
    const int r0 = (tid >> 4) * 2;

    // tables
    for (int p = tid; p < 512; p += NT) {
        if (p < 496) {
            int pp = p, i = 0;
            while (pp >= 31 - i) { pp -= 31 - i; i++; }
            s_ii[p] = (unsigned char)i;
            s_jj[p] = (unsigned char)(i + 1 + pp);
        } else { s_ii[p] = 0; s_jj[p] = 1; }
    }
    for (int idx = tid; idx < 1024; idx += NT) {
        int nn = idx >> 5, k = idx & 31;
        s_jl[idx] = (k < nn)
            ? (unsigned short)(k * 31 - ((k * (k - 1)) >> 1) + (nn - k - 1))
            : (unsigned short)0xFFFF;
    }
    stage_Bt(P.ee2_w, Bth, Btl, tid);
    if (tid < 64) b2s[tid] = P.ee2_b[tid];
    __syncthreads();

    const float* zb0 = P.z + (size_t)(2 * blockIdx.x) * (16 * 32 * 32);
    const float* zb1 = zb0 + 16 * 32 * 32;

    // ---- Phase A: ya/yb = src @ ee1_w (streamed; ee1_b folded into ya; pitch YAP) ----
    {
        float accA[2][2][4], accB[2][2][4];
#pragma unroll
        for (int j = 0; j < 4; j++) {
            float bv = P.ee1_b[c0 + j];
            accA[0][0][j] = bv; accA[0][1][j] = bv; accA[1][0][j] = bv; accA[1][1][j] = bv;
            accB[0][0][j] = 0.f; accB[0][1][j] = 0.f; accB[1][0][j] = 0.f; accB[1][1][j] = 0.f;
        }
#pragma unroll 1
        for (int ch = 0; ch < 8; ch++) {
            for (int idx = tid; idx < 2048; idx += NT) {
                int o = idx >> 6, fl = idx & 63;
                int t = 2 * ch + (fl >> 5), e = fl & 31;
                int off = (t * 32 + o) * 32 + e;
                float v0 = zb0[off], v1 = zb1[off];
                if (t > 0) { v0 -= zb0[off - 1024]; v1 -= zb1[off - 1024]; }
                sc0[o * 64 + fl] = v0;
                sc1[o * 64 + fl] = v1;
            }
            __syncthreads();
            acc_chunk2(sc0, sc1, P.ee1_w + ch * 4096, accA, r0, c0);
            acc_chunk2(sc0, sc1, P.ee1_w + 512 * 64 + ch * 4096, accB, r0, c0);
            __syncthreads();
        }
#pragma unroll
        for (int i = 0; i < 2; i++)
#pragma unroll
            for (int j = 0; j < 4; j++) {
                ya0[(r0 + i) * YAP + c0 + j] = accA[0][i][j];
                ya1[(r0 + i) * YAP + c0 + j] = accA[1][i][j];
                yb0[(r0 + i) * YAP + c0 + j] = accB[0][i][j];
                yb1[(r0 + i) * YAP + c0 + j] = accB[1][i][j];
            }
    }
    __syncthreads();

    // ---- ee edge block (HMMA) ----
    edge_full(ya0, ya1, yb0, yb1, Bth, Btl, b2s, P.ee3_w, P.ee3_b,
              h2f, Gs0, Gs1, agg0, agg1, s_ii, s_jj, s_jl, tid);

    // ---- ne MLP (ya buffers reused pitch-64 as hidden) ----
    layer2<64, false, false, 64>(agg0, agg1, P.ne1_w + 512 * 64, P.ne1_b, ya0, ya1, tid);
    {
        float acc[2][2][4];
#pragma unroll
        for (int i = 0; i < 2; i++)
#pragma unroll
            for (int j = 0; j < 4; j++) {
                acc[0][i][j] = ya0[(r0 + i) * 64 + c0 + j];   // own cells
                acc[1][i][j] = ya1[(r0 + i) * 64 + c0 + j];
            }
#pragma unroll 1
        for (int ch = 0; ch < 8; ch++) {
            for (int idx = tid; idx < 2048; idx += NT) {
                int o = idx >> 6, fl = idx & 63;
                int t = 2 * ch + (fl >> 5), e = fl & 31;
                int off = (t * 32 + o) * 32 + e;
                float v0 = zb0[off], v1 = zb1[off];
                if (t > 0) { v0 -= zb0[off - 1024]; v1 -= zb1[off - 1024]; }
                sc0[o * 64 + fl] = v0;
                sc1[o * 64 + fl] = v1;
            }
            __syncthreads();
            acc_chunk2(sc0, sc1, P.ne1_w + ch * 4096, acc, r0, c0);
            __syncthreads();
        }
#pragma unroll
        for (int i = 0; i < 2; i++)
#pragma unroll
            for (int j = 0; j < 4; j++) {
                ya0[(r0 + i) * 64 + c0 + j] = fmaxf(acc[0][i][j], 0.f);
                ya1[(r0 + i) * 64 + c0 + j] = fmaxf(acc[1][i][j], 0.f);
            }
    }
    __syncthreads();
    layer2<64, false, true, 64>(ya0, ya1, P.ne2_w, P.ne2_b, sc0, sc1, tid);
    __syncthreads();
    layer_small_2(sc0, sc1, 64, P.ne3_w, P.ne3_b, t0, t1, 32, true, tid);
    __syncthreads();
    layer_small_2(t0, t1, 32, P.ne4_w, P.ne4_b, sc0, sc1, 32, false, tid);  // z_impl
    __syncthreads();

    // zc = concat(z[b,-1], z_impl); restage le2 weights/bias
    const float* zl0 = zb0 + 15 * 32 * 32;
    const float* zl1 = zb1 + 15 * 32 * 32;
    for (int idx = tid; idx < 2048; idx += NT) {
        int o = idx >> 6, c = idx & 63;
        zc0[idx] = (c < 32) ? zl0[o * 32 + c] : sc0[o * 32 + (c - 32)];
        zc1[idx] = (c < 32) ? zl1[o * 32 + c] : sc1[o * 32 + (c - 32)];
    }
    __syncthreads();
    stage_Bt(P.le2_w, Bth, Btl, tid);
    if (tid < 64) b2s[tid] = P.le2_b[tid];
    __syncthreads();

    // ---- rollout ----
    const int ostride = P.t_future * 1024;
    float* out0 = P.out + (size_t)(2 * blockIdx.x) * ostride;
    float* out1 = out0 + ostride;
#pragma unroll 1
    for (int t = 0; t < P.t_future; t++) {
        layer2<64, false, false, YAP>(zc0, zc1, P.le1_w,           P.le1_b, ya0, ya1, tid);
        layer2<64, false, false, YAP>(zc0, zc1, P.le1_w + 64 * 64, nullptr, yb0, yb1, tid);
        __syncthreads();
        edge_full(ya0, ya1, yb0, yb1, Bth, Btl, b2s, P.le3_w, P.le3_b,
                  h2f, Gs0, Gs1, agg0, agg1, s_ii, s_jj, s_jl, tid);

        layer2<64, false, false, 64>(zc0, zc1, P.lt1_w,            P.lt1_b, sc0, sc1, tid);
        layer2<64, true,  true,  64>(agg0, agg1, P.lt1_w + 64 * 64, nullptr, sc0, sc1, tid);
        __syncthreads();
        layer2<64, false, true, 64>(sc0, sc1, P.lt2_w, P.lt2_b, t0, t1, tid);
        __syncthreads();
        layer_small_2(t0, t1, 64, P.lt3_w, P.lt3_b, sc0, sc1, 32, true, tid);
        __syncthreads();
        layer_small_2(sc0, sc1, 32, P.lt4_w, P.lt4_b, t0, t1, 16, true, tid);
        __syncthreads();
        layer2<16, false, false, 64>(t0, t1, P.lt5_w, P.lt5_b, sc0, sc1, tid);  // delta
        __syncthreads();

        for (int idx = tid; idx < 2048; idx += NT) {
            float zn0 = zc0[idx] + sc0[idx];
            float zn1 = zc1[idx] + sc1[idx];
            zc0[idx] = zn0; zc1[idx] = zn1;
            int o = idx >> 6, c = idx & 63;
            if (c < 32) {
                out0[t * 1024 + o * 32 + c] = zn0;
                out1[t * 1024 + o * 32 + c] = zn1;
            }
        }
        __syncthreads();
    }
}

extern "C" void kernel_launch(void* const* d_in, const int* in_sizes, int n_in,
                              void* d_out, int out_size)
{
    Params P;
    int i = 0;
    P.z     = (const float*)d_in[i++];
    P.ee1_w = (const float*)d_in[i++]; P.ee1_b = (const float*)d_in[i++];
    P.ee2_w = (const float*)d_in[i++]; P.ee2_b = (const float*)d_in[i++];
    P.ee3_w = (const float*)d_in[i++]; P.ee3_b = (const float*)d_in[i++];
    P.ne1_w = (const float*)d_in[i++]; P.ne1_b = (const float*)d_in[i++];
    P.ne2_w = (const float*)d_in[i++]; P.ne2_b = (const float*)d_in[i++];
    P.ne3_w = (const float*)d_in[i++]; P.ne3_b = (const float*)d_in[i++];
    P.ne4_w = (const float*)d_in[i++]; P.ne4_b = (const float*)d_in[i++];
    P.le1_w = (const float*)d_in[i++]; P.le1_b = (const float*)d_in[i++];
    P.le2_w = (const float*)d_in[i++]; P.le2_b = (const float*)d_in[i++];
    P.le3_w = (const float*)d_in[i++]; P.le3_b = (const float*)d_in[i++];
    P.lt1_w = (const float*)d_in[i++]; P.lt1_b = (const float*)d_in[i++];
    P.lt2_w = (const float*)d_in[i++]; P.lt2_b = (const float*)d_in[i++];
    P.lt3_w = (const float*)d_in[i++]; P.lt3_b = (const float*)d_in[i++];
    P.lt4_w = (const float*)d_in[i++]; P.lt4_b = (const float*)d_in[i++];
    P.lt5_w = (const float*)d_in[i++]; P.lt5_b = (const float*)d_in[i++];
    P.out = (float*)d_out;
    P.t_future = out_size / (256 * 32 * 32);

    cudaFuncSetAttribute(RelationalLatentDynamics_82849919140105_kernel,
                         cudaFuncAttributeMaxDynamicSharedMemorySize, SMEM_BYTES);
    RelationalLatentDynamics_82849919140105_kernel<<<128, NT, SMEM_BYTES>>>(P);
}